// round 16
// baseline (speedup 1.0000x reference)
#include <cuda_runtime.h>
#include <cstdint>

// D3PM q_sample — bit-exact vs JAX threefry, partitionable mode:
//   split:  key_i = (o0, o1) of threefry2x32((0,42), (0, i))     [foldlike]
//   bits32: bits[i] = o0 ^ o1 of threefry2x32(key, (0, flat_idx)),
//           flat_idx row-major over (B, L, N).
//
// Output (float32): [0,R) noised_structure, [R,2R) noised_sequence, [2R,2R+B) t.
//
// Pruning theorem: argmax is ALWAYS x0 or MASK -> 2 RNG draws per element.
//
// R15 post-mortem: MUFU (2x __logf/elem, rt 8/SMSP) was the binding pipe
// (1771 ops/SMSP * 8 = 14.2k cyc ~ measured 8.4us). This round evicts MUFU:
//   scaled log: 2^23*(-log2 f) = (0x3F800000 - i) - 2^23*sigma(m),
//   sigma(m) = log2(1+m) - m ~= 0.34*m*(1-m)  (|err| <= ~0.007 log2-units).
//   int->float via 2^23 magic-number (two 15-bit halves; no I2F, no MUFU).
//   decision diff = WL2 - C*WL1;  band = 1e5*(1+C) + 2e-5*(WL2 + C*WL1)
//   covers sigma err (84k scaled), magic/FFMA rounding, C rel err, and the
//   reference's own fp32 boundary rounding (~1e-5 rel). In-band (P~1%) ->
//   __noinline__ exact fallback replicating the reference bit-for-bit.

#define TINYF  1.17549435e-38f
#define EPSF   1e-10f

__host__ __device__ __forceinline__ unsigned rotl32(unsigned x, int r) {
#ifdef __CUDA_ARCH__
    return __funnelshift_l(x, x, r);
#else
    return (x << r) | (x >> (32 - r));
#endif
}

// Standard threefry2x32, 20 rounds (matches jax/_src/prng.py lowering).
__host__ __device__ __forceinline__ void threefry2x32(
    unsigned k0, unsigned k1, unsigned m0, unsigned m1,
    unsigned& o0, unsigned& o1)
{
    const unsigned ks2 = 0x1BD11BDAu ^ k0 ^ k1;
    unsigned x0 = m0 + k0;
    unsigned x1 = m1 + k1;
#define TF_R(r) { x0 += x1; x1 = rotl32(x1, (r)) ^ x0; }
    TF_R(13) TF_R(15) TF_R(26) TF_R(6)
    x0 += k1;  x1 += ks2 + 1u;
    TF_R(17) TF_R(29) TF_R(16) TF_R(24)
    x0 += ks2; x1 += k0 + 2u;
    TF_R(13) TF_R(15) TF_R(26) TF_R(6)
    x0 += k0;  x1 += k1 + 3u;
    TF_R(17) TF_R(29) TF_R(16) TF_R(24)
    x0 += k1;  x1 += ks2 + 4u;
    TF_R(13) TF_R(15) TF_R(26) TF_R(6)
    x0 += ks2; x1 += k0 + 5u;
#undef TF_R
    o0 = x0; o1 = x1;
}

__device__ __forceinline__ unsigned jax_bits32(unsigned ka, unsigned kb, unsigned i) {
    unsigned o0, o1;
    threefry2x32(ka, kb, 0u, i, o0, o1);
    return o0 ^ o1;
}

// f stage, bit-identical to the reference's clamped uniform:
//   u = bitcast((bits>>9)|0x3f800000)-1; f = max(tiny, u+tiny)  [(1-tiny)->1.0f]
__device__ __forceinline__ float f_from_bits(unsigned bits) {
    float u = __uint_as_float(0x3f800000u | (bits >> 9)) - 1.0f;
    return fmaxf(TINYF, u + TINYF);
}

// Scaled approximate negative log2: WL ~= 2^23 * (-log2 f), no MUFU.
// f is normal, f in [2^-126, 1). |WL - true| <= ~84000 (sigma approx) + <=128
// (magic/FFMA rounding), always nonnegative-ish near 0.
__device__ __forceinline__ float wl_from_f(float f) {
    unsigned i = __float_as_uint(f);
    unsigned W = 0x3F800000u - i;                 // (127-e)*2^23 - mbits
    float fhi = __uint_as_float(0x4B000000u | (W >> 15)) - 8388608.0f;
    float flo = __uint_as_float(0x4B000000u | (W & 0x7FFFu)) - 8388608.0f;
    float m1p = __uint_as_float((i & 0x7FFFFFu) | 0x3F800000u);  // 1+m in [1,2)
    float s   = (m1p - 1.0f) * (2.0f - m1p);       // m*(1-m)
    float wl  = fmaf(fhi, 32768.0f, flo);          // float(W), err <= 64
    return fmaf(s, -2852126.75f, wl);              // - 0.34*2^23 * m(1-m)
}

// Exact decision, replicating the reference computation bit-for-bit.
// Out of line: only executed inside the uncertainty band (P ~ 1%).
__device__ __noinline__ float exact_decide(
    unsigned b1, unsigned b2, float a, int x0, int MASK)
{
    float f1 = f_from_bits(b1);
    float f2 = f_from_bits(b2);
    float vx = -logf(-logf(f1)) + logf(a + EPSF);
    float vm = -logf(-logf(f2)) + logf((1.0f - a) + EPSF);
    if (vx > vm) return (float)x0;
    if (vm > vx) return (float)MASK;
    return (float)((x0 < MASK) ? x0 : MASK);   // argmax first-max tie-break
}

// One element. C = (1-a+eps)/(a+eps); bandP = 1e5*(1+C) per pair.
__device__ __forceinline__ float sample_one(
    int r, int x0, float C, float bandP, float a,
    unsigned ka, unsigned kb, int N, int MASK)
{
    if (x0 == MASK) return (float)x0;   // combined channel always wins
    unsigned base = (unsigned)r * (unsigned)N;
    unsigned b1 = jax_bits32(ka, kb, base + (unsigned)x0);
    unsigned b2 = jax_bits32(ka, kb, base + (unsigned)MASK);

    float wl1 = wl_from_f(f_from_bits(b1));
    float wl2 = wl_from_f(f_from_bits(b2));

    float thr  = C * wl1;
    float diff = wl2 - thr;
    float band = fmaf(2e-5f, wl2 + thr, bandP);

    float res = (diff > 0.0f) ? (float)x0 : (float)MASK;
    if (fabsf(diff) <= band)
        res = exact_decide(b1, b2, a, x0, MASK);
    return res;
}

__global__ __launch_bounds__(256)
void d3pm_kernel(const int* __restrict__ pA, const int* __restrict__ pB,
                 const int* __restrict__ t, const float* __restrict__ alpha,
                 float* __restrict__ out,
                 unsigned ksa, unsigned ksb,
                 unsigned kqa, unsigned kqb,
                 int rows, int Bv, int shift, int L, int fast)
{
    // per-warp swap detect (no block sync): which big array is structure?
    // (sequence values always <= 32; structure exceeds 32 w.p. 1-8e-20)
    int lane = threadIdx.x & 31;
    int v = (lane < 16) ? pA[lane] : pB[lane - 16];
    unsigned big = __ballot_sync(0xffffffffu, v > 32);
    const bool swap = ((big & 0xFFFFu) == 0u);
    const int* structure = swap ? pB : pA;
    const int* sequence  = swap ? pA : pB;

    const int total = 2 * rows + Bv;
    const int gt    = blockIdx.x * blockDim.x + threadIdx.x;

    if (fast) {
        // 2 elements per thread; groups 2-aligned, never straddle segments
        // (rows % 2 == 0) nor batch boundaries (L % 2 == 0, r0 even).
        int j = gt * 2;
        if (j >= total) return;

        if (j < 2 * rows) {
            const bool isS = (j < rows);
            const int  r0  = isS ? j : j - rows;
            const int  N    = isS ? 516 : 33;
            const int  MASK = isS ? 3   : 32;
            const unsigned ka = isS ? ksa : kqa;
            const unsigned kb = isS ? ksb : kqb;
            const int* src = isS ? structure : sequence;

            // per pair: one t/alpha load, one division, one band constant
            int   tv = t[r0 >> shift];
            float a  = alpha[tv];
            float C  = __fdividef((1.0f - a) + EPSF, a + EPSF);
            float bandP = fmaf(1e5f, C, 1e5f);

            int2 x = *reinterpret_cast<const int2*>(src + r0);

            float2 o;
            o.x = sample_one(r0 + 0, x.x, C, bandP, a, ka, kb, N, MASK);
            o.y = sample_one(r0 + 1, x.y, C, bandP, a, ka, kb, N, MASK);
            *reinterpret_cast<float2*>(out + j) = o;
        } else {
            // t passthrough (tiny tail; scalar)
            #pragma unroll
            for (int q = 0; q < 2; q++) {
                int jj = j + q;
                if (jj < total) out[jj] = (float)t[jj - 2 * rows];
            }
        }
    } else {
        // generic fallback (any geometry): exact everywhere
        for (int j = gt; j < total; j += gridDim.x * blockDim.x) {
            if (j < 2 * rows) {
                const bool isS = (j < rows);
                const int  r   = isS ? j : j - rows;
                int   tv = t[(shift >= 0) ? (r >> shift) : (r / L)];
                float a  = alpha[tv];
                int   x0   = isS ? structure[r] : sequence[r];
                int   N    = isS ? 516 : 33;
                int   MASK = isS ? 3   : 32;
                unsigned ka = isS ? ksa : kqa;
                unsigned kb = isS ? ksb : kqb;
                if (x0 == MASK) { out[j] = (float)x0; continue; }
                unsigned base = (unsigned)r * (unsigned)N;
                unsigned b1 = jax_bits32(ka, kb, base + (unsigned)x0);
                unsigned b2 = jax_bits32(ka, kb, base + (unsigned)MASK);
                out[j] = exact_decide(b1, b2, a, x0, MASK);
            } else {
                out[j] = (float)t[j - 2 * rows];
            }
        }
    }
}

extern "C" void kernel_launch(void* const* d_in, const int* in_sizes, int n_in,
                              void* d_out, int out_size)
{
    // Bind by size: two largest (equal) = structure/sequence candidates
    // (disambiguated on-device); of the two small ones, t's size divides
    // rows while alpha's (T+1 = 501) does not.
    int idx[4] = {0, 1, 2, 3};
    for (int i = 0; i < 3; i++)
        for (int k = i + 1; k < 4; k++)
            if (in_sizes[idx[k]] > in_sizes[idx[i]]) {
                int tmp = idx[i]; idx[i] = idx[k]; idx[k] = tmp;
            }
    const int iA = idx[0], iB = idx[1];
    int iT = idx[3], iAl = idx[2];
    const int rows = in_sizes[iA];
    if (rows % in_sizes[iT] != 0 && rows % in_sizes[iAl] == 0) {
        int tmp = iT; iT = iAl; iAl = tmp;
    }

    const int*   pA    = (const int*)  d_in[iA];
    const int*   pB    = (const int*)  d_in[iB];
    const int*   t     = (const int*)  d_in[iT];
    const float* alpha = (const float*)d_in[iAl];
    const int    Bv    = in_sizes[iT];
    const int    L     = rows / Bv;

    int shift = -1;
    if ((L & (L - 1)) == 0) { shift = 0; while ((1 << shift) < L) shift++; }
    const int fast = (shift >= 0) && (L % 2 == 0) && (rows % 2 == 0);

    // key = jax.random.key(42) -> (0, 42)
    // partitionable (foldlike) split: key_i = (o0, o1) of F((0,42), (0, i))
    unsigned ksa, ksb, kqa, kqb;
    threefry2x32(0u, 42u, 0u, 0u, ksa, ksb);   // ks (structure)
    threefry2x32(0u, 42u, 0u, 1u, kqa, kqb);   // kq (sequence)

    const int total = 2 * rows + Bv;
    int blocks;
    if (fast) {
        const int groups = (total + 1) / 2;
        blocks = (groups + 255) / 256;
    } else {
        blocks = (total + 255) / 256;
        if (blocks > 2048) blocks = 2048;
    }

    d3pm_kernel<<<blocks, 256>>>(
        pA, pB, t, alpha, (float*)d_out,
        ksa, ksb, kqa, kqb, rows, Bv, shift, L, fast);
}

// round 17
// speedup vs baseline: 1.2657x; 1.2657x over previous
#include <cuda_runtime.h>
#include <cstdint>

// D3PM q_sample — bit-exact vs JAX threefry, partitionable mode:
//   split:  key_i = (o0, o1) of threefry2x32((0,42), (0, i))     [foldlike]
//   bits32: bits[i] = o0 ^ o1 of threefry2x32(key, (0, flat_idx)),
//           flat_idx row-major over (B, L, N).
//
// Output (float32): [0,R) noised_structure, [R,2R) noised_sequence, [2R,2R+B) t.
//
// Pruning theorem: argmax is ALWAYS x0 or MASK -> 2 RNG draws per element.
//
// R16 post-mortem: MUFU was never binding (warp-wide ops: ~56/SMSP, 450 cyc);
// kernel is LATENCY-exposed (issue 58%). Critical chain was
// ballot -> ptr select -> x0 global load -> threefry(b1). This round keeps
// R15's math exactly (best so far) and restructures for overlap:
//   - load BOTH candidate arrays' int2 up front (select after ballot),
//   - run the mask-draw threefry chains (index-only) while loads fly,
//   - then x0-draw chains, then alpha/C/band (off critical path), decisions.

#define TINYF  1.17549435e-38f
#define EPSF   1e-10f

__host__ __device__ __forceinline__ unsigned rotl32(unsigned x, int r) {
#ifdef __CUDA_ARCH__
    return __funnelshift_l(x, x, r);
#else
    return (x << r) | (x >> (32 - r));
#endif
}

// Standard threefry2x32, 20 rounds (matches jax/_src/prng.py lowering).
__host__ __device__ __forceinline__ void threefry2x32(
    unsigned k0, unsigned k1, unsigned m0, unsigned m1,
    unsigned& o0, unsigned& o1)
{
    const unsigned ks2 = 0x1BD11BDAu ^ k0 ^ k1;
    unsigned x0 = m0 + k0;
    unsigned x1 = m1 + k1;
#define TF_R(r) { x0 += x1; x1 = rotl32(x1, (r)) ^ x0; }
    TF_R(13) TF_R(15) TF_R(26) TF_R(6)
    x0 += k1;  x1 += ks2 + 1u;
    TF_R(17) TF_R(29) TF_R(16) TF_R(24)
    x0 += ks2; x1 += k0 + 2u;
    TF_R(13) TF_R(15) TF_R(26) TF_R(6)
    x0 += k0;  x1 += k1 + 3u;
    TF_R(17) TF_R(29) TF_R(16) TF_R(24)
    x0 += k1;  x1 += ks2 + 4u;
    TF_R(13) TF_R(15) TF_R(26) TF_R(6)
    x0 += ks2; x1 += k0 + 5u;
#undef TF_R
    o0 = x0; o1 = x1;
}

__device__ __forceinline__ unsigned jax_bits32(unsigned ka, unsigned kb, unsigned i) {
    unsigned o0, o1;
    threefry2x32(ka, kb, 0u, i, o0, o1);
    return o0 ^ o1;
}

// f stage, bit-identical to the reference's clamped uniform:
//   u = bitcast((bits>>9)|0x3f800000)-1; f = max(tiny, u+tiny)  [(1-tiny)->1.0f]
__device__ __forceinline__ float f_from_bits(unsigned bits) {
    float u = __uint_as_float(0x3f800000u | (bits >> 9)) - 1.0f;
    return fmaxf(TINYF, u + TINYF);
}

// Exact decision, replicating the reference computation bit-for-bit.
// Out of line: only executed inside the uncertainty band (P ~ 1e-4).
__device__ __noinline__ float exact_decide(
    unsigned b1, unsigned b2, float a, int x0, int MASK)
{
    float f1 = f_from_bits(b1);
    float f2 = f_from_bits(b2);
    float vx = -logf(-logf(f1)) + logf(a + EPSF);
    float vm = -logf(-logf(f2)) + logf((1.0f - a) + EPSF);
    if (vx > vm) return (float)x0;
    if (vm > vx) return (float)MASK;
    return (float)((x0 < MASK) ? x0 : MASK);   // argmax first-max tie-break
}

// R15 margin decision: w = -__logf(f) (MUFU), C = (1-a+eps)/(a+eps),
// band = 1e-4*thr + 1e-6*(1+C) covers all fp32/MUFU boundary error.
__device__ __forceinline__ float decide(
    int x0, float w1, float w2, unsigned b1, unsigned b2,
    float C, float bandK, float a, int MASK)
{
    if (x0 == MASK) return (float)x0;   // combined channel always wins
    float thr  = w1 * C;
    float diff = w2 - thr;
    float band = fmaf(1e-4f, thr, bandK);
    float res = (diff > 0.0f) ? (float)x0 : (float)MASK;
    if (fabsf(diff) <= band)
        res = exact_decide(b1, b2, a, x0, MASK);
    return res;
}

__global__ __launch_bounds__(256)
void d3pm_kernel(const int* __restrict__ pA, const int* __restrict__ pB,
                 const int* __restrict__ t, const float* __restrict__ alpha,
                 float* __restrict__ out,
                 unsigned ksa, unsigned ksb,
                 unsigned kqa, unsigned kqb,
                 int rows, int Bv, int shift, int L, int fast)
{
    const int total = 2 * rows + Bv;
    const int gt    = blockIdx.x * blockDim.x + threadIdx.x;
    const int lane  = threadIdx.x & 31;

    if (fast) {
        int j = gt * 2;
        if (j >= total) return;

        if (j < 2 * rows) {
            const bool isS = (j < rows);
            const int  r0  = isS ? j : j - rows;
            const int  N    = isS ? 516 : 33;
            const int  MASK = isS ? 3   : 32;
            const unsigned ka = isS ? ksa : kqa;
            const unsigned kb = isS ? ksb : kqb;

            // ---- issue ALL loads up front (no dependency on ballot) ----
            int2 xa = *reinterpret_cast<const int2*>(pA + r0);
            int2 xb = *reinterpret_cast<const int2*>(pB + r0);
            int  tv = t[r0 >> shift];
            int  dv = (lane < 16) ? pA[lane] : pB[lane - 16];  // detect sample

            // ---- mask-draw threefry chains: depend only on r0 ----
            unsigned base0 = (unsigned)r0 * (unsigned)N;
            unsigned base1 = base0 + (unsigned)N;
            unsigned b2a = jax_bits32(ka, kb, base0 + (unsigned)MASK);
            unsigned b2b = jax_bits32(ka, kb, base1 + (unsigned)MASK);
            float w2a = -__logf(f_from_bits(b2a));
            float w2b = -__logf(f_from_bits(b2b));

            // ---- resolve swap + x0 (loads have had ~150 instrs to land) ----
            unsigned big = __ballot_sync(0xffffffffu, dv > 32);
            const bool swap = ((big & 0xFFFFu) == 0u);  // pA is sequence
            // structure = swap ? pB : pA ; sequence = swap ? pA : pB
            int2 x = isS ? (swap ? xb : xa) : (swap ? xa : xb);

            // ---- x0-draw chains ----
            unsigned b1a = jax_bits32(ka, kb, base0 + (unsigned)x.x);
            unsigned b1b = jax_bits32(ka, kb, base1 + (unsigned)x.y);
            float w1a = -__logf(f_from_bits(b1a));
            float w1b = -__logf(f_from_bits(b1b));

            // ---- logits constants (off critical path) ----
            float a = alpha[tv];
            float C = __fdividef((1.0f - a) + EPSF, a + EPSF);
            float bandK = fmaf(1e-6f, C, 1e-6f);

            float2 o;
            o.x = decide(x.x, w1a, w2a, b1a, b2a, C, bandK, a, MASK);
            o.y = decide(x.y, w1b, w2b, b1b, b2b, C, bandK, a, MASK);
            *reinterpret_cast<float2*>(out + j) = o;
        } else {
            // t passthrough (tiny tail; scalar) — still participate in ballot
            __ballot_sync(0xffffffffu, 0);
            #pragma unroll
            for (int q = 0; q < 2; q++) {
                int jj = j + q;
                if (jj < total) out[jj] = (float)t[jj - 2 * rows];
            }
        }
    } else {
        // generic fallback (any geometry): exact everywhere
        int dv = (lane < 16) ? pA[lane] : pB[lane - 16];
        unsigned big = __ballot_sync(0xffffffffu, dv > 32);
        const bool swap = ((big & 0xFFFFu) == 0u);
        const int* structure = swap ? pB : pA;
        const int* sequence  = swap ? pA : pB;

        for (int j = gt; j < total; j += gridDim.x * blockDim.x) {
            if (j < 2 * rows) {
                const bool isS = (j < rows);
                const int  r   = isS ? j : j - rows;
                int   tv = t[(shift >= 0) ? (r >> shift) : (r / L)];
                float a  = alpha[tv];
                int   x0   = isS ? structure[r] : sequence[r];
                int   N    = isS ? 516 : 33;
                int   MASK = isS ? 3   : 32;
                unsigned ka = isS ? ksa : kqa;
                unsigned kb = isS ? ksb : kqb;
                if (x0 == MASK) { out[j] = (float)x0; continue; }
                unsigned base = (unsigned)r * (unsigned)N;
                unsigned b1 = jax_bits32(ka, kb, base + (unsigned)x0);
                unsigned b2 = jax_bits32(ka, kb, base + (unsigned)MASK);
                out[j] = exact_decide(b1, b2, a, x0, MASK);
            } else {
                out[j] = (float)t[j - 2 * rows];
            }
        }
    }
}

extern "C" void kernel_launch(void* const* d_in, const int* in_sizes, int n_in,
                              void* d_out, int out_size)
{
    // Bind by size: two largest (equal) = structure/sequence candidates
    // (disambiguated on-device); of the two small ones, t's size divides
    // rows while alpha's (T+1 = 501) does not.
    int idx[4] = {0, 1, 2, 3};
    for (int i = 0; i < 3; i++)
        for (int k = i + 1; k < 4; k++)
            if (in_sizes[idx[k]] > in_sizes[idx[i]]) {
                int tmp = idx[i]; idx[i] = idx[k]; idx[k] = tmp;
            }
    const int iA = idx[0], iB = idx[1];
    int iT = idx[3], iAl = idx[2];
    const int rows = in_sizes[iA];
    if (rows % in_sizes[iT] != 0 && rows % in_sizes[iAl] == 0) {
        int tmp = iT; iT = iAl; iAl = tmp;
    }

    const int*   pA    = (const int*)  d_in[iA];
    const int*   pB    = (const int*)  d_in[iB];
    const int*   t     = (const int*)  d_in[iT];
    const float* alpha = (const float*)d_in[iAl];
    const int    Bv    = in_sizes[iT];
    const int    L     = rows / Bv;

    int shift = -1;
    if ((L & (L - 1)) == 0) { shift = 0; while ((1 << shift) < L) shift++; }
    const int fast = (shift >= 0) && (L % 2 == 0) && (rows % 2 == 0);

    // key = jax.random.key(42) -> (0, 42)
    // partitionable (foldlike) split: key_i = (o0, o1) of F((0,42), (0, i))
    unsigned ksa, ksb, kqa, kqb;
    threefry2x32(0u, 42u, 0u, 0u, ksa, ksb);   // ks (structure)
    threefry2x32(0u, 42u, 0u, 1u, kqa, kqb);   // kq (sequence)

    const int total = 2 * rows + Bv;
    int blocks;
    if (fast) {
        const int groups = (total + 1) / 2;
        blocks = (groups + 255) / 256;
    } else {
        blocks = (total + 255) / 256;
        if (blocks > 2048) blocks = 2048;
    }

    d3pm_kernel<<<blocks, 256>>>(
        pA, pB, t, alpha, (float*)d_out,
        ksa, ksb, kqa, kqb, rows, Bv, shift, L, fast);
}